// round 8
// baseline (speedup 1.0000x reference)
#include <cuda_runtime.h>
#include <cstdint>
#include <cstddef>

#define BATCH    64
#define SEQ      2048
#define INPUT    8
#define HIDDEN   512
#define NUM_SEEDS 4
#define DD       12
#define OUTK     10
#define ALPHA_F  0.1f
#define K1_F     (0.1f * (500.0f/512.0f))
#define QSCALE   4194304.0f          /* 2^22 fixed-point scale for warp reduction */
#define QINV     (1.0f/4194304.0f)
#define HPL      16                  /* hidden units per lane (512/32) */

// ---------------- scratch (static __device__ — no allocation) ----------------
__device__ float g_m0[NUM_SEEDS][HIDDEN];
__device__ float g_m1[NUM_SEEDS][HIDDEN];
__device__ float g_n0[NUM_SEEDS][HIDDEN];
__device__ float g_n1[NUM_SEEDS][HIDDEN];
__device__ float g_I [NUM_SEEDS][HIDDEN][INPUT];
__device__ float g_ix[(size_t)BATCH * SEQ * HIDDEN];   // 256 MB: a = 0.1*(I x_t)

// native tanh (MUFU.TANH, sm_75+): 1 MUFU op, ~16cyc; rel err ~2^-11.
__device__ __forceinline__ float fast_tanh(float x) {
    float r;
    asm("tanh.approx.f32 %0, %1;" : "=f"(r) : "f"(x));
    return r;
}

// ---------------- kernel 1: combined mixture -> m, n, I ----------------
__global__ void setup_kernel(const float* __restrict__ means,
                             const float* __restrict__ L,
                             const float* __restrict__ mw,
                             const float* __restrict__ seeds) {
    __shared__ float Lc[DD][DD];
    __shared__ float mc[DD];
    int tid = threadIdx.x;

    float w0 = fmaxf(mw[0], 1e-6f);
    float w1 = fmaxf(mw[1], 1e-6f);
    float inv = 1.0f / (w0 + w1);
    w0 *= inv; w1 *= inv;

    if (tid < DD * DD) {
        int d = tid / DD, e = tid - d * DD;
        float a = L[d * DD + e];
        float c = L[DD * DD + d * DD + e];
        float v = 0.0f;
        if (e < d) {
            v = w0 * a + w1 * c;
        } else if (e == d) {
            v = w0 * (fabsf(a - 1e-12f) + 1e-12f)
              + w1 * (fabsf(c - 1e-12f) + 1e-12f);
        }
        Lc[d][e] = v;
    }
    if (tid < DD) mc[tid] = w0 * means[tid] + w1 * means[DD + tid];
    __syncthreads();

    int g = blockIdx.x * blockDim.x + tid;      // 0..2047 = s*512 + h
    int s = g >> 9, h = g & 511;

    float sd[DD];
    #pragma unroll
    for (int e = 0; e < DD; e++) sd[e] = seeds[(size_t)g * DD + e];

    float comb[DD];
    #pragma unroll
    for (int d = 0; d < DD; d++) {
        float v = mc[d];
        for (int e = 0; e <= d; e++) v = fmaf(Lc[d][e], sd[e], v);
        comb[d] = v;
    }
    g_m0[s][h] = comb[0];
    g_m1[s][h] = comb[1];
    g_n0[s][h] = comb[2];
    g_n1[s][h] = comb[3];
    #pragma unroll
    for (int i = 0; i < INPUT; i++) g_I[s][h][i] = comb[4 + i];
}

// ---------------- kernel 2: output channels 2..9 (x-only, via pinv@span == I) ----
__global__ __launch_bounds__(32) void xout_kernel(const float* __restrict__ x,
                                                  float* __restrict__ out) {
    const int b = blockIdx.x;
    const int lane = threadIdx.x;
    if (lane >= INPUT) return;

    const float* src = x + (size_t)b * SEQ * INPUT + lane;
    float* ob = out + (size_t)b * SEQ * OUTK + 2 + lane;

    float acc = 0.0f;
    #pragma unroll 8
    for (int t = 0; t < SEQ; t++) {
        acc = fmaf(0.9f, acc, ALPHA_F * src[(size_t)t * INPUT]);
        ob[(size_t)t * OUTK] = acc;
    }
}

// ---------------- kernel 3: precompute a[b][t][h] = 0.1 * (I x_t)[h] ----------------
// grid (SEQ/64, BATCH), 128 threads, 4 h per thread per t. DRAM-write bound.
__global__ __launch_bounds__(128) void ixprep_kernel(const float* __restrict__ x,
                                                     const int* __restrict__ cur_seeds) {
    const int b = blockIdx.y;
    const int s = cur_seeds[b];
    __shared__ float sI[HIDDEN * INPUT];   // 16 KB, [h][i], prescaled by ALPHA
    for (int i = threadIdx.x; i < HIDDEN * INPUT; i += 128)
        sI[i] = ALPHA_F * ((const float*)&g_I[s][0][0])[i];
    __syncthreads();

    const int t0 = blockIdx.x * 64;
    const float* xb = x + ((size_t)b * SEQ + t0) * INPUT;
    float* ob = g_ix + ((size_t)b * SEQ + t0) * HIDDEN + threadIdx.x * 4;
    const float* w = &sI[threadIdx.x * 4 * INPUT];

    #pragma unroll 2
    for (int tt = 0; tt < 64; tt++) {
        float4 xa = *(const float4*)(xb + (size_t)tt * INPUT);
        float4 xv = *(const float4*)(xb + (size_t)tt * INPUT + 4);
        float r[4];
        #pragma unroll
        for (int c = 0; c < 4; c++) {
            const float* wc = w + c * INPUT;
            float v =        wc[0] * xa.x;
            v = fmaf(wc[1], xa.y, v);
            v = fmaf(wc[2], xa.z, v);
            v = fmaf(wc[3], xa.w, v);
            v = fmaf(wc[4], xv.x, v);
            v = fmaf(wc[5], xv.y, v);
            v = fmaf(wc[6], xv.z, v);
            v = fmaf(wc[7], xv.w, v);
            r[c] = v;
        }
        *(float4*)(ob + (size_t)tt * HIDDEN) = make_float4(r[0], r[1], r[2], r[3]);
    }
}

// ---------------- kernel 4: the sequential RNN scan — ONE WARP PER CHAIN ----------------
// 32 threads, 16 hidden per lane. All-reduce = redux.sync (fixed point, 2^22).
// No smem, no barriers, no cross-warp anything. a_t streamed from g_ix with a
// 2-step register prefetch.
__global__ __launch_bounds__(32, 1) void rnn_kernel(const int* __restrict__ cur_seeds,
                                                    float* __restrict__ out) {
    const int b = blockIdx.x;
    const int lane = threadIdx.x;
    const int s = cur_seeds[b];
    const int h0 = lane * HPL;

    float N0[HPL], N1[HPL], M0k[HPL], M1k[HPL];
    #pragma unroll
    for (int g = 0; g < HPL / 4; g++) {
        float4 n0 = *(const float4*)&g_n0[s][h0 + g * 4];
        float4 n1 = *(const float4*)&g_n1[s][h0 + g * 4];
        float4 m0 = *(const float4*)&g_m0[s][h0 + g * 4];
        float4 m1 = *(const float4*)&g_m1[s][h0 + g * 4];
        N0[g*4+0] = n0.x * QSCALE; N0[g*4+1] = n0.y * QSCALE;
        N0[g*4+2] = n0.z * QSCALE; N0[g*4+3] = n0.w * QSCALE;
        N1[g*4+0] = n1.x * QSCALE; N1[g*4+1] = n1.y * QSCALE;
        N1[g*4+2] = n1.z * QSCALE; N1[g*4+3] = n1.w * QSCALE;
        const float KQ = K1_F * QINV;   // fold K1 and fixed-point scale into m
        M0k[g*4+0] = m0.x * KQ; M0k[g*4+1] = m0.y * KQ;
        M0k[g*4+2] = m0.z * KQ; M0k[g*4+3] = m0.w * KQ;
        M1k[g*4+0] = m1.x * KQ; M1k[g*4+1] = m1.y * KQ;
        M1k[g*4+2] = m1.z * KQ; M1k[g*4+3] = m1.w * KQ;
    }

    const float* ap = g_ix + (size_t)b * SEQ * HIDDEN + h0;
    float2* ob01 = (float2*)(out + (size_t)b * SEQ * OUTK);   // channels 0,1
    const float K1S = K1_F * QINV;

    float h[HPL];
    #pragma unroll
    for (int j = 0; j < HPL; j++) h[j] = 0.0f;
    float oa = 0.0f, obv = 0.0f;

    // 2-deep register prefetch of a_t
    float A0[HPL], A1[HPL];
    #pragma unroll
    for (int g = 0; g < HPL / 4; g++) {
        *(float4*)&A0[g*4] = *(const float4*)(ap + 0 * HIDDEN + g * 4);
        *(float4*)&A1[g*4] = *(const float4*)(ap + 1 * HIDDEN + g * 4);
    }

    #define RNN_STEP(T, ABUF)                                                     \
    {                                                                             \
        float q0 = 0.0f, q1 = 0.0f;                                               \
        _Pragma("unroll")                                                         \
        for (int j = 0; j < HPL; j++) {                                           \
            float th = fast_tanh(h[j]);                                           \
            q0 = fmaf(N0[j], th, q0);                                             \
            q1 = fmaf(N1[j], th, q1);                                             \
        }                                                                         \
        int iq0 = __float2int_rn(q0);                                             \
        int iq1 = __float2int_rn(q1);                                             \
        iq0 = __reduce_add_sync(0xffffffffu, iq0);                                \
        iq1 = __reduce_add_sync(0xffffffffu, iq1);                                \
        float p0 = (float)iq0;                                                    \
        float p1 = (float)iq1;                                                    \
        _Pragma("unroll")                                                         \
        for (int j = 0; j < HPL; j++)                                             \
            h[j] = fmaf(0.9f, h[j], fmaf(M0k[j], p0, fmaf(M1k[j], p1, ABUF[j]))); \
        if (lane == 0) {                                                          \
            oa  = fmaf(0.9f, oa,  K1S * p0);                                      \
            obv = fmaf(0.9f, obv, K1S * p1);                                      \
            ob01[(size_t)(T) * (OUTK / 2)] = make_float2(oa, obv);                \
        }                                                                         \
        /* prefetch t+2 into ABUF (clamped; 2 steps ~ covers DRAM latency) */     \
        int tf = (T) + 2 < SEQ ? (T) + 2 : SEQ - 1;                               \
        const float* apf = ap + (size_t)tf * HIDDEN;                              \
        _Pragma("unroll")                                                         \
        for (int g = 0; g < HPL / 4; g++)                                         \
            *(float4*)&ABUF[g*4] = *(const float4*)(apf + g * 4);                 \
    }

    for (int t = 0; t < SEQ; t += 2) {
        RNN_STEP(t,     A0);
        RNN_STEP(t + 1, A1);
    }
    #undef RNN_STEP
}

// ---------------- launch ----------------
extern "C" void kernel_launch(void* const* d_in, const int* in_sizes, int n_in,
                              void* d_out, int out_size) {
    const float* x     = (const float*)d_in[0];   // (64,2048,8)
    const float* means = (const float*)d_in[1];   // (2,12)
    const float* L     = (const float*)d_in[2];   // (2,12,12)
    const float* mw    = (const float*)d_in[3];   // (2,)
    const float* seeds = (const float*)d_in[4];   // (4,512,12)
    const int*   cs    = (const int*)d_in[5];     // (64,)
    float* out = (float*)d_out;                   // (64,2048,10)

    setup_kernel<<<8, 256>>>(means, L, mw, seeds);
    xout_kernel<<<BATCH, 32>>>(x, out);
    ixprep_kernel<<<dim3(SEQ / 64, BATCH), 128>>>(x, cs);
    rnn_kernel<<<BATCH, 32>>>(cs, out);
}

// round 10
// speedup vs baseline: 3.0319x; 3.0319x over previous
#include <cuda_runtime.h>
#include <cstdint>
#include <cstddef>

#define BATCH    64
#define SEQ      2048
#define INPUT    8
#define HIDDEN   512
#define NUM_SEEDS 4
#define DD       12
#define OUTK     10
#define ALPHA_F  0.1f
#define K1_F     (0.1f * (500.0f/512.0f))
#define QSCALE   4194304.0f          /* 2^22 fixed-point scale for warp reduction */
#define QINV     (1.0f/4194304.0f)

// ---------------- scratch (static __device__ — no allocation) ----------------
__device__ float g_m0[NUM_SEEDS][HIDDEN];
__device__ float g_m1[NUM_SEEDS][HIDDEN];
__device__ float g_n0[NUM_SEEDS][HIDDEN];
__device__ float g_n1[NUM_SEEDS][HIDDEN];
__device__ float g_I [NUM_SEEDS][HIDDEN][INPUT];

// native tanh (MUFU.TANH): 1 MUFU op, ~16cyc; rel err ~2^-11.
__device__ __forceinline__ float fast_tanh(float x) {
    float r;
    asm("tanh.approx.f32 %0, %1;" : "=f"(r) : "f"(x));
    return r;
}

// ---- packed f32x2 helpers (Blackwell FFMA2 via PTX) ----
__device__ __forceinline__ unsigned long long pk2(float lo, float hi) {
    unsigned long long r;
    asm("mov.b64 %0, {%1, %2};" : "=l"(r) : "f"(lo), "f"(hi));
    return r;
}
__device__ __forceinline__ float2 up2(unsigned long long v) {
    float2 r;
    asm("mov.b64 {%0, %1}, %2;" : "=f"(r.x), "=f"(r.y) : "l"(v));
    return r;
}
__device__ __forceinline__ unsigned long long fma2(unsigned long long a,
                                                   unsigned long long b,
                                                   unsigned long long c) {
    unsigned long long r;
    asm("fma.rn.f32x2 %0, %1, %2, %3;" : "=l"(r) : "l"(a), "l"(b), "l"(c));
    return r;
}

// ---------------- kernel 1: combined mixture -> m, n, I ----------------
__global__ void setup_kernel(const float* __restrict__ means,
                             const float* __restrict__ L,
                             const float* __restrict__ mw,
                             const float* __restrict__ seeds) {
    __shared__ float Lc[DD][DD];
    __shared__ float mc[DD];
    int tid = threadIdx.x;

    float w0 = fmaxf(mw[0], 1e-6f);
    float w1 = fmaxf(mw[1], 1e-6f);
    float inv = 1.0f / (w0 + w1);
    w0 *= inv; w1 *= inv;

    if (tid < DD * DD) {
        int d = tid / DD, e = tid - d * DD;
        float a = L[d * DD + e];
        float c = L[DD * DD + d * DD + e];
        float v = 0.0f;
        if (e < d) {
            v = w0 * a + w1 * c;
        } else if (e == d) {
            v = w0 * (fabsf(a - 1e-12f) + 1e-12f)
              + w1 * (fabsf(c - 1e-12f) + 1e-12f);
        }
        Lc[d][e] = v;
    }
    if (tid < DD) mc[tid] = w0 * means[tid] + w1 * means[DD + tid];
    __syncthreads();

    int g = blockIdx.x * blockDim.x + tid;      // 0..2047 = s*512 + h
    int s = g >> 9, h = g & 511;

    float sd[DD];
    #pragma unroll
    for (int e = 0; e < DD; e++) sd[e] = seeds[(size_t)g * DD + e];

    float comb[DD];
    #pragma unroll
    for (int d = 0; d < DD; d++) {
        float v = mc[d];
        for (int e = 0; e <= d; e++) v = fmaf(Lc[d][e], sd[e], v);
        comb[d] = v;
    }
    g_m0[s][h] = comb[0];
    g_m1[s][h] = comb[1];
    g_n0[s][h] = comb[2];
    g_n1[s][h] = comb[3];
    #pragma unroll
    for (int i = 0; i < INPUT; i++) g_I[s][h][i] = comb[4 + i];
}

// ---------------- kernel 2: output channels 2..9 (x-only, via pinv@span == I) ----
__global__ __launch_bounds__(32) void xout_kernel(const float* __restrict__ x,
                                                  float* __restrict__ out) {
    const int b = blockIdx.x;
    const int lane = threadIdx.x;
    if (lane >= INPUT) return;

    const float* src = x + (size_t)b * SEQ * INPUT + lane;
    float* ob = out + (size_t)b * SEQ * OUTK + 2 + lane;

    float acc = 0.0f;
    #pragma unroll 8
    for (int t = 0; t < SEQ; t++) {
        acc = fmaf(0.9f, acc, ALPHA_F * src[(size_t)t * INPUT]);
        ob[(size_t)t * OUTK] = acc;
    }
}

// ---------------- kernel 3: the sequential RNN scan ----------------
// R6 skeleton (128 thr, redux fixed-point, STS/BAR/LDS exchange), plus:
//  - elementwise blocks in packed f32x2 (h, aix, update all unit-paired)
//  - out[0:2] scan moved to warp 3 (highest arbiter priority; warp 0 no
//    longer the systematic barrier straggler)
//  - 2-step unroll: smem parity compile-time per half
__global__ __launch_bounds__(128, 1) void rnn_kernel(const float* __restrict__ x,
                                                     const int* __restrict__ cur_seeds,
                                                     float* __restrict__ out) {
    const int b = blockIdx.x;
    const int tid = threadIdx.x;
    const int wid = tid >> 5, lane = tid & 31;
    const int s = cur_seeds[b];
    const int h0 = tid * 4;

    // n prescaled by 2^22 (scalar — q-dot consumes scalar tanh outputs)
    float4 N0 = *(const float4*)&g_n0[s][h0];
    float4 N1 = *(const float4*)&g_n1[s][h0];
    N0.x *= QSCALE; N0.y *= QSCALE; N0.z *= QSCALE; N0.w *= QSCALE;
    N1.x *= QSCALE; N1.y *= QSCALE; N1.z *= QSCALE; N1.w *= QSCALE;

    // m packed over unit pairs, K1*2^-22 folded in
    const float KQ = K1_F * QINV;
    float4 m0 = *(const float4*)&g_m0[s][h0];
    float4 m1 = *(const float4*)&g_m1[s][h0];
    const unsigned long long M0A = pk2(m0.x * KQ, m0.y * KQ);
    const unsigned long long M0B = pk2(m0.z * KQ, m0.w * KQ);
    const unsigned long long M1A = pk2(m1.x * KQ, m1.y * KQ);
    const unsigned long long M1B = pk2(m1.z * KQ, m1.w * KQ);

    // I packed over unit pairs, ALPHA folded in: IwA[i]=(I[h0][i],I[h0+1][i])
    unsigned long long IwA[INPUT], IwB[INPUT];
    #pragma unroll
    for (int i = 0; i < INPUT; i++) {
        IwA[i] = pk2(ALPHA_F * g_I[s][h0 + 0][i], ALPHA_F * g_I[s][h0 + 1][i]);
        IwB[i] = pk2(ALPHA_F * g_I[s][h0 + 2][i], ALPHA_F * g_I[s][h0 + 3][i]);
    }

    const float* xb = x + (size_t)b * SEQ * INPUT;
    float2* ob01 = (float2*)(out + (size_t)b * SEQ * OUTK);   // channels 0,1
    const float K1S = K1_F * QINV;
    const unsigned long long C9 = pk2(0.9f, 0.9f);
    const unsigned long long ZU = 0ull;                        // (0.0f, 0.0f)

    __shared__ __align__(16) int isp[2][2][4];   // [parity][r][warp]

    unsigned long long hA = ZU, hB = ZU;          // packed (h0,h1),(h2,h3)
    float oa = 0.0f, obv = 0.0f;                  // warp-3 out scans
    const bool outw = (wid == 3) && (lane == 0);

    // double-buffered x rows (2 steps in flight)
    float4 xA0 = *(const float4*)(xb + 0), xB0 = *(const float4*)(xb + 4);
    float4 xA1 = *(const float4*)(xb + 8), xB1 = *(const float4*)(xb + 12);

    #define RNN_STEP(PAR, T, XA, XB)                                              \
    {                                                                             \
        float2 hx = up2(hA), hy = up2(hB);                                        \
        float th0 = fast_tanh(hx.x);                                              \
        float th1 = fast_tanh(hx.y);                                              \
        float th2 = fast_tanh(hy.x);                                              \
        float th3 = fast_tanh(hy.y);                                              \
        float q0 = fmaf(N0.x, th0, N0.y * th1) + fmaf(N0.z, th2, N0.w * th3);     \
        float q1 = fmaf(N1.x, th0, N1.y * th1) + fmaf(N1.z, th2, N1.w * th3);     \
        int iq0 = __float2int_rn(q0);                                             \
        int iq1 = __float2int_rn(q1);                                             \
        iq0 = __reduce_add_sync(0xffffffffu, iq0);                                \
        iq1 = __reduce_add_sync(0xffffffffu, iq1);                                \
        if (lane == 0) { isp[PAR][0][wid] = iq0; isp[PAR][1][wid] = iq1; }        \
        /* aix (packed over unit pairs) fills the pre-barrier window */           \
        unsigned long long xd0 = pk2(XA.x, XA.x), xd1 = pk2(XA.y, XA.y);          \
        unsigned long long xd2 = pk2(XA.z, XA.z), xd3 = pk2(XA.w, XA.w);          \
        unsigned long long xd4 = pk2(XB.x, XB.x), xd5 = pk2(XB.y, XB.y);          \
        unsigned long long xd6 = pk2(XB.z, XB.z), xd7 = pk2(XB.w, XB.w);          \
        unsigned long long aA = fma2(IwA[0], xd0, ZU);                            \
        unsigned long long aB = fma2(IwB[0], xd0, ZU);                            \
        aA = fma2(IwA[1], xd1, aA);  aB = fma2(IwB[1], xd1, aB);                  \
        aA = fma2(IwA[2], xd2, aA);  aB = fma2(IwB[2], xd2, aB);                  \
        aA = fma2(IwA[3], xd3, aA);  aB = fma2(IwB[3], xd3, aB);                  \
        aA = fma2(IwA[4], xd4, aA);  aB = fma2(IwB[4], xd4, aB);                  \
        aA = fma2(IwA[5], xd5, aA);  aB = fma2(IwB[5], xd5, aB);                  \
        aA = fma2(IwA[6], xd6, aA);  aB = fma2(IwB[6], xd6, aB);                  \
        aA = fma2(IwA[7], xd7, aA);  aB = fma2(IwB[7], xd7, aB);                  \
        __syncthreads();                                                          \
        int4 P0 = *(const int4*)&isp[PAR][0][0];                                  \
        int4 P1 = *(const int4*)&isp[PAR][1][0];                                  \
        int s0 = (P0.x + P0.y) + (P0.z + P0.w);                                   \
        int s1 = (P1.x + P1.y) + (P1.z + P1.w);                                   \
        float p0 = (float)s0;                                                     \
        float p1 = (float)s1;                                                     \
        unsigned long long p0d = pk2(p0, p0), p1d = pk2(p1, p1);                  \
        hA = fma2(C9, hA, fma2(M0A, p0d, fma2(M1A, p1d, aA)));                    \
        hB = fma2(C9, hB, fma2(M0B, p0d, fma2(M1B, p1d, aB)));                    \
        if (outw) {                                                               \
            oa  = fmaf(0.9f, oa,  K1S * p0);                                      \
            obv = fmaf(0.9f, obv, K1S * p1);                                      \
            ob01[(size_t)(T) * (OUTK / 2)] = make_float2(oa, obv);                \
        }                                                                         \
    }

    for (int t = 0; t < SEQ; t += 2) {
        // prefetch rows t+2, t+3 (clamped) — consumed next iteration
        int tf = (t + 2 <= SEQ - 2) ? t + 2 : SEQ - 2;
        float4 nA0 = *(const float4*)(xb + (size_t)tf * INPUT);
        float4 nB0 = *(const float4*)(xb + (size_t)tf * INPUT + 4);
        float4 nA1 = *(const float4*)(xb + (size_t)(tf + 1) * INPUT);
        float4 nB1 = *(const float4*)(xb + (size_t)(tf + 1) * INPUT + 4);

        RNN_STEP(0, t,     xA0, xB0);
        RNN_STEP(1, t + 1, xA1, xB1);

        xA0 = nA0; xB0 = nB0; xA1 = nA1; xB1 = nB1;
    }
    #undef RNN_STEP
}

// ---------------- launch ----------------
extern "C" void kernel_launch(void* const* d_in, const int* in_sizes, int n_in,
                              void* d_out, int out_size) {
    const float* x     = (const float*)d_in[0];   // (64,2048,8)
    const float* means = (const float*)d_in[1];   // (2,12)
    const float* L     = (const float*)d_in[2];   // (2,12,12)
    const float* mw    = (const float*)d_in[3];   // (2,)
    const float* seeds = (const float*)d_in[4];   // (4,512,12)
    const int*   cs    = (const int*)d_in[5];     // (64,)
    float* out = (float*)d_out;                   // (64,2048,10)

    setup_kernel<<<8, 256>>>(means, L, mw, seeds);
    xout_kernel<<<BATCH, 32>>>(x, out);
    rnn_kernel<<<BATCH, 128>>>(x, cs, out);
}